// round 10
// baseline (speedup 1.0000x reference)
#include <cuda_runtime.h>
#include <cuda_bf16.h>
#include <mma.h>
#include <math.h>
#include <cstdint>

using namespace nvcuda;

#define Bb 128
#define Ss 256
#define Ii 512
#define Oo 512
#define Hh 1024
#define G3 3072
#define RWS (Ss*Bb)
#define NCTA 96

// ---------------- scratch ----------------
__device__ __align__(16) float g_yT[16777216];    // [s*B+b][I]
__device__ int   g_idx[RWS];
__device__ __align__(16) float g_gi[100663296];   // [s*B+b][3H]
__device__ __align__(16) float g_gh4[4*Bb*G3];    // 4 K-split partials
__device__ __align__(16) float g_h[Bb*Hh];        // current hidden state
__device__ __align__(16) float g_hsB[33554432];   // [b*S+s][H]
__device__ __align__(16) float g_lg[16777216];    // raw logits
__device__ __align__(16) float g_WtgtT[Oo*G3];
__device__ int   g_bar[512];                      // step barrier counters
__device__ __align__(16) __nv_bfloat16 g_WhhHi[G3*1024], g_WhhLo[G3*1024];
__device__ __align__(16) __nv_bfloat16 g_WihHi[G3*1024], g_WihLo[G3*1024];
__device__ __align__(16) __nv_bfloat16 g_LwHi[Oo*1024],  g_LwLo[Oo*1024];

typedef wmma::fragment<wmma::matrix_a, 16,16,16, __nv_bfloat16, wmma::row_major> FragA;
typedef wmma::fragment<wmma::matrix_b, 16,16,16, __nv_bfloat16, wmma::col_major> FragB;
typedef wmma::fragment<wmma::accumulator, 16,16,16, float> FragC;

#define SROW 20
#define SROW_E 40

// convert 16 fp32 -> hi/lo bf16x2 quads
__device__ __forceinline__ void cvt16(const float4 v0, const float4 v1, uint4& hi, uint4& lo){
    __nv_bfloat16 h0, h1, l0, l1;
    h0=__float2bfloat16(v0.x); h1=__float2bfloat16(v0.y);
    l0=__float2bfloat16(v0.x-__bfloat162float(h0)); l1=__float2bfloat16(v0.y-__bfloat162float(h1));
    hi.x = ((uint32_t)__bfloat16_as_ushort(h1)<<16) | __bfloat16_as_ushort(h0);
    lo.x = ((uint32_t)__bfloat16_as_ushort(l1)<<16) | __bfloat16_as_ushort(l0);
    h0=__float2bfloat16(v0.z); h1=__float2bfloat16(v0.w);
    l0=__float2bfloat16(v0.z-__bfloat162float(h0)); l1=__float2bfloat16(v0.w-__bfloat162float(h1));
    hi.y = ((uint32_t)__bfloat16_as_ushort(h1)<<16) | __bfloat16_as_ushort(h0);
    lo.y = ((uint32_t)__bfloat16_as_ushort(l1)<<16) | __bfloat16_as_ushort(l0);
    h0=__float2bfloat16(v1.x); h1=__float2bfloat16(v1.y);
    l0=__float2bfloat16(v1.x-__bfloat162float(h0)); l1=__float2bfloat16(v1.y-__bfloat162float(h1));
    hi.z = ((uint32_t)__bfloat16_as_ushort(h1)<<16) | __bfloat16_as_ushort(h0);
    lo.z = ((uint32_t)__bfloat16_as_ushort(l1)<<16) | __bfloat16_as_ushort(l0);
    h0=__float2bfloat16(v1.z); h1=__float2bfloat16(v1.w);
    l0=__float2bfloat16(v1.z-__bfloat162float(h0)); l1=__float2bfloat16(v1.w-__bfloat162float(h1));
    hi.w = ((uint32_t)__bfloat16_as_ushort(h1)<<16) | __bfloat16_as_ushort(h0);
    lo.w = ((uint32_t)__bfloat16_as_ushort(l1)<<16) | __bfloat16_as_ushort(l0);
}

// ---------------- generic wmma GEMM (R7-proven, for gi/logits) ----------------
__device__ __forceinline__ void wmma_gemm(
    const float* __restrict__ Asrc, int lda, int mBase,
    const __nv_bfloat16* __restrict__ BHi, const __nv_bfloat16* __restrict__ BLo,
    int ldb, int nBase, int k0, int nChunks,
    float* __restrict__ dst, int ldd)
{
    __shared__ __align__(16) uint32_t sAHi[128*SROW], sALo[128*SROW];
    __shared__ __align__(16) uint32_t sBHi[128*SROW], sBLo[128*SROW];
    int t = threadIdx.x;
    FragC acc[2][4];
    #pragma unroll
    for (int mi = 0; mi < 2; ++mi)
        #pragma unroll
        for (int ni = 0; ni < 4; ++ni) wmma::fill_fragment(acc[mi][ni], 0.f);
    int w = t >> 5;
    int rowOff = (w&3)*32, colOff = (w>>2)*64;
    const __nv_bfloat16* eAh = reinterpret_cast<const __nv_bfloat16*>(sAHi);
    const __nv_bfloat16* eAl = reinterpret_cast<const __nv_bfloat16*>(sALo);
    const __nv_bfloat16* eBh = reinterpret_cast<const __nv_bfloat16*>(sBHi);
    const __nv_bfloat16* eBl = reinterpret_cast<const __nv_bfloat16*>(sBLo);
    for (int c = 0; c < nChunks; ++c){
        int kc = k0 + c*32;
        #pragma unroll
        for (int it = 0; it < 2; ++it){
            int idx = it*256 + t;
            int row = idx >> 2, seg = idx & 3;
            const float* p = Asrc + (size_t)(mBase + row)*lda + kc + seg*8;
            float4 v0 = *reinterpret_cast<const float4*>(p);
            float4 v1 = *reinterpret_cast<const float4*>(p + 4);
            uint4 hi, lo; cvt16(v0, v1, hi, lo);
            *reinterpret_cast<uint4*>(sAHi + row*SROW + seg*4) = hi;
            *reinterpret_cast<uint4*>(sALo + row*SROW + seg*4) = lo;
        }
        #pragma unroll
        for (int it = 0; it < 2; ++it){
            int idx = it*256 + t;
            int row = idx >> 2, seg = idx & 3;
            size_t off = (size_t)(nBase + row)*ldb + kc + seg*8;
            *reinterpret_cast<uint4*>(sBHi + row*SROW + seg*4) =
                *reinterpret_cast<const uint4*>(BHi + off);
            *reinterpret_cast<uint4*>(sBLo + row*SROW + seg*4) =
                *reinterpret_cast<const uint4*>(BLo + off);
        }
        __syncthreads();
        #pragma unroll
        for (int ks = 0; ks < 2; ++ks){
            FragA ah[2], al[2];
            #pragma unroll
            for (int mi = 0; mi < 2; ++mi){
                wmma::load_matrix_sync(ah[mi], eAh + (rowOff + mi*16)*SROW_E + ks*16, SROW_E);
                wmma::load_matrix_sync(al[mi], eAl + (rowOff + mi*16)*SROW_E + ks*16, SROW_E);
            }
            #pragma unroll
            for (int ni = 0; ni < 4; ++ni){
                FragB bh, bl;
                wmma::load_matrix_sync(bh, eBh + (colOff + ni*16)*SROW_E + ks*16, SROW_E);
                wmma::load_matrix_sync(bl, eBl + (colOff + ni*16)*SROW_E + ks*16, SROW_E);
                #pragma unroll
                for (int mi = 0; mi < 2; ++mi){
                    wmma::mma_sync(acc[mi][ni], ah[mi], bh, acc[mi][ni]);
                    wmma::mma_sync(acc[mi][ni], ah[mi], bl, acc[mi][ni]);
                    wmma::mma_sync(acc[mi][ni], al[mi], bh, acc[mi][ni]);
                }
            }
        }
        __syncthreads();
    }
    #pragma unroll
    for (int mi = 0; mi < 2; ++mi)
        #pragma unroll
        for (int ni = 0; ni < 4; ++ni)
            wmma::store_matrix_sync(dst + (size_t)(mBase + rowOff + mi*16)*ldd
                                        + nBase + colOff + ni*16,
                                    acc[mi][ni], ldd, wmma::mem_row_major);
}

// ---------------- persistent fused recurrence ----------------
__device__ __forceinline__ void grid_bar(int i){
    __syncthreads();
    __threadfence();
    if (threadIdx.x == 0){
        atomicAdd(&g_bar[i], 1);
        while (*(volatile int*)&g_bar[i] < NCTA) {}
        __threadfence();
    }
    __syncthreads();
}

__global__ void __launch_bounds__(256, 1) k_recur(const float* __restrict__ bhh,
                                                  float* __restrict__ pre_out){
    extern __shared__ uint32_t smb[];
    // layout (u32): BHi chunks [ch]*2560 (8 ch), BLo +20480, AHi 40960, ALo 43520
    int t = threadIdx.x;
    int nt = blockIdx.x >> 2, kz = blockIdx.x & 3;
    int nBase = nt*128, k00 = kz*256;
    int gt = blockIdx.x*256 + t;

    // stage Whh slice into smem once
    for (int ch = 0; ch < 8; ++ch){
        int kc = k00 + ch*32;
        #pragma unroll
        for (int it = 0; it < 2; ++it){
            int idx = it*256 + t;
            int row = idx >> 2, seg = idx & 3;
            size_t off = (size_t)(nBase + row)*1024 + kc + seg*8;
            *reinterpret_cast<uint4*>(smb + ch*2560 + row*SROW + seg*4) =
                *reinterpret_cast<const uint4*>(g_WhhHi + off);
            *reinterpret_cast<uint4*>(smb + 20480 + ch*2560 + row*SROW + seg*4) =
                *reinterpret_cast<const uint4*>(g_WhhLo + off);
        }
    }
    __syncthreads();

    int w = t >> 5;
    int rowOff = (w&3)*32, colOff = (w>>2)*64;
    const __nv_bfloat16* eAh = reinterpret_cast<const __nv_bfloat16*>(smb + 40960);
    const __nv_bfloat16* eAl = reinterpret_cast<const __nv_bfloat16*>(smb + 43520);
    float* dst = g_gh4 + (size_t)kz*Bb*G3;

    for (int s = 0; s < Ss; ++s){
        FragC acc[2][4];
        #pragma unroll
        for (int mi = 0; mi < 2; ++mi)
            #pragma unroll
            for (int ni = 0; ni < 4; ++ni) wmma::fill_fragment(acc[mi][ni], 0.f);

        for (int ch = 0; ch < 8; ++ch){
            int kc = k00 + ch*32;
            #pragma unroll
            for (int it = 0; it < 2; ++it){
                int idx = it*256 + t;
                int row = idx >> 2, seg = idx & 3;
                const float* p = g_h + (size_t)row*1024 + kc + seg*8;
                float4 v0 = __ldcg(reinterpret_cast<const float4*>(p));
                float4 v1 = __ldcg(reinterpret_cast<const float4*>(p + 4));
                uint4 hi, lo; cvt16(v0, v1, hi, lo);
                *reinterpret_cast<uint4*>(smb + 40960 + row*SROW + seg*4) = hi;
                *reinterpret_cast<uint4*>(smb + 43520 + row*SROW + seg*4) = lo;
            }
            __syncthreads();
            const __nv_bfloat16* eBh = reinterpret_cast<const __nv_bfloat16*>(smb + ch*2560);
            const __nv_bfloat16* eBl = reinterpret_cast<const __nv_bfloat16*>(smb + 20480 + ch*2560);
            #pragma unroll
            for (int ks = 0; ks < 2; ++ks){
                FragA ah[2], al[2];
                #pragma unroll
                for (int mi = 0; mi < 2; ++mi){
                    wmma::load_matrix_sync(ah[mi], eAh + (rowOff + mi*16)*SROW_E + ks*16, SROW_E);
                    wmma::load_matrix_sync(al[mi], eAl + (rowOff + mi*16)*SROW_E + ks*16, SROW_E);
                }
                #pragma unroll
                for (int ni = 0; ni < 4; ++ni){
                    FragB bh, bl;
                    wmma::load_matrix_sync(bh, eBh + (colOff + ni*16)*SROW_E + ks*16, SROW_E);
                    wmma::load_matrix_sync(bl, eBl + (colOff + ni*16)*SROW_E + ks*16, SROW_E);
                    #pragma unroll
                    for (int mi = 0; mi < 2; ++mi){
                        wmma::mma_sync(acc[mi][ni], ah[mi], bh, acc[mi][ni]);
                        wmma::mma_sync(acc[mi][ni], ah[mi], bl, acc[mi][ni]);
                        wmma::mma_sync(acc[mi][ni], al[mi], bh, acc[mi][ni]);
                    }
                }
            }
            __syncthreads();
        }
        #pragma unroll
        for (int mi = 0; mi < 2; ++mi)
            #pragma unroll
            for (int ni = 0; ni < 4; ++ni)
                wmma::store_matrix_sync(dst + (size_t)(rowOff + mi*16)*G3
                                            + nBase + colOff + ni*16,
                                        acc[mi][ni], G3, wmma::mem_row_major);
        grid_bar(2*s);

        // gates phase, distributed over all 24576 threads
        for (int e = gt; e < Bb*Hh; e += NCTA*256){
            int b = e >> 10, j = e & 1023;
            size_t gio = ((size_t)(s*Bb + b))*G3 + j;
            float i_r = g_gi[gio], i_z = g_gi[gio + Hh], i_n = g_gi[gio + 2*Hh];
            size_t gho = (size_t)b*G3 + j;
            float h_r = bhh[j], h_z = bhh[Hh + j], h_n = bhh[2*Hh + j];
            #pragma unroll
            for (int kq = 0; kq < 4; ++kq){
                const float* p = g_gh4 + (size_t)kq*Bb*G3 + gho;
                h_r += __ldcg(p); h_z += __ldcg(p + Hh); h_n += __ldcg(p + 2*Hh);
            }
            float rg = 1.f/(1.f + expf(-(i_r + h_r)));
            float zg = 1.f/(1.f + expf(-(i_z + h_z)));
            float pre = i_n + rg*h_n;
            float ng = tanhf(pre);
            float hp = __ldcg(g_h + (size_t)b*Hh + j);
            float hy = ng + zg*(hp - ng);
            g_h[(size_t)b*Hh + j] = hy;
            g_hsB[((size_t)b*Ss + s)*Hh + j] = hy;
            pre_out[((size_t)b*Ss + s)*Hh + j] = pre;
        }
        grid_bar(2*s + 1);
    }
}

// ---------------- prep kernels ----------------
__global__ void k_idx(const float* __restrict__ gt, const float* __restrict__ gotoken){
    int w = (blockIdx.x*blockDim.x + threadIdx.x) >> 5;
    int lane = threadIdx.x & 31;
    if (w >= RWS) return;
    int s = w / Bb, b = w % Bb;
    const float* src = (s == 0) ? gotoken : gt + ((size_t)b*Ss + (s-1))*Oo;
    int found = Oo - 1;
    for (int o = lane; o < Oo; o += 32)
        if (src[o] > 0.5f) found = o;
    #pragma unroll
    for (int off = 16; off; off >>= 1)
        found = min(found, __shfl_xor_sync(0xffffffffu, found, off));
    if (lane == 0) g_idx[w] = found;
}

__global__ void k_yT(const float* __restrict__ y){
    size_t t = (size_t)blockIdx.x*blockDim.x + threadIdx.x;
    if (t >= (size_t)RWS*Ii) return;
    int i = (int)(t % Ii); int r = (int)(t / Ii);
    int s = r / Bb, b = r % Bb;
    g_yT[t] = y[((size_t)b*Ss + s)*Ii + i];
}

__global__ void k_h0(const float* __restrict__ hx){
    int t = blockIdx.x*blockDim.x + threadIdx.x;
    if (t < Bb*Hh) g_h[t] = hx[t];
    if (blockIdx.x == 0){ g_bar[threadIdx.x] = 0; g_bar[threadIdx.x + 256] = 0; }
}

__global__ void k_convWhh(const float* __restrict__ W){
    int t = blockIdx.x*blockDim.x + threadIdx.x;
    float v = W[t];
    __nv_bfloat16 h = __float2bfloat16(v);
    g_WhhHi[t] = h;
    g_WhhLo[t] = __float2bfloat16(v - __bfloat162float(h));
}
__global__ void k_convWih(const float* __restrict__ W){
    int t = blockIdx.x*blockDim.x + threadIdx.x;
    float v = W[t];
    __nv_bfloat16 h = __float2bfloat16(v);
    g_WihHi[t] = h;
    g_WihLo[t] = __float2bfloat16(v - __bfloat162float(h));
}
__global__ void k_convLw(const float* __restrict__ W){
    int t = blockIdx.x*blockDim.x + threadIdx.x;
    float v = W[t];
    __nv_bfloat16 h = __float2bfloat16(v);
    g_LwHi[t] = h;
    g_LwLo[t] = __float2bfloat16(v - __bfloat162float(h));
}

__global__ void k_prepT(const float* __restrict__ Wih){
    __shared__ float tile[32][33];
    int gB = blockIdx.x*32, oB = blockIdx.y*32;
    int tx = threadIdx.x, ty = threadIdx.y;
    #pragma unroll
    for (int j = 0; j < 32; j += 8)
        tile[ty+j][tx] = Wih[(size_t)(gB + ty + j)*1024 + 512 + oB + tx];
    __syncthreads();
    #pragma unroll
    for (int j = 0; j < 32; j += 8)
        g_WtgtT[(size_t)(oB + ty + j)*3072 + gB + tx] = tile[tx][ty+j];
}

// ---------------- GEMM kernels ----------------
__global__ void __launch_bounds__(256, 1) k_giW(){
    wmma_gemm(g_yT, 512, blockIdx.y*128,
              g_WihHi, g_WihLo, 1024, blockIdx.x*128, 0, 16,
              g_gi, 3072);
}

__global__ void __launch_bounds__(256, 1) k_lwW(){
    wmma_gemm(g_hsB, 1024, blockIdx.y*128,
              g_LwHi, g_LwLo, 1024, blockIdx.x*128, 0, 32,
              g_lg, 512);
}

// gi epilogue: add bih + one-hot gather column
__global__ void k_giBias(const float* __restrict__ bih){
    int idx = blockIdx.x*blockDim.x + threadIdx.x;
    int row = idx / 768;
    int n4 = (idx - row*768)*4;
    int id = g_idx[row];
    float4 v = *reinterpret_cast<float4*>(g_gi + (size_t)row*3072 + n4);
    float4 b = *reinterpret_cast<const float4*>(bih + n4);
    float4 wv = *reinterpret_cast<const float4*>(g_WtgtT + (size_t)id*3072 + n4);
    v.x += b.x + wv.x; v.y += b.y + wv.y; v.z += b.z + wv.z; v.w += b.w + wv.w;
    *reinterpret_cast<float4*>(g_gi + (size_t)row*3072 + n4) = v;
}

// ---------------- softmax + argmax ----------------
__global__ void k_softmax(const float* __restrict__ lb,
                          float* __restrict__ probs, float* __restrict__ samp){
    __shared__ float sv[128];
    __shared__ int   si[128];
    int row = blockIdx.x;
    int t = threadIdx.x;
    const float* lgi = g_lg + (size_t)row*Oo;
    float v[4];
    #pragma unroll
    for (int i = 0; i < 4; ++i) v[i] = lgi[t + i*128] + lb[t + i*128];
    float lmax = v[0]; int lidx = t;
    #pragma unroll
    for (int i = 1; i < 4; ++i)
        if (v[i] > lmax){ lmax = v[i]; lidx = t + i*128; }
    sv[t] = lmax; si[t] = lidx; __syncthreads();
    for (int off = 64; off; off >>= 1){
        if (t < off){
            float v2 = sv[t+off]; int i2 = si[t+off];
            if (v2 > sv[t] || (v2 == sv[t] && i2 < si[t])){ sv[t] = v2; si[t] = i2; }
        }
        __syncthreads();
    }
    float rmax = sv[0]; int ridx = si[0];
    __syncthreads();
    float e[4]; float ls = 0.f;
    #pragma unroll
    for (int i = 0; i < 4; ++i){ e[i] = expf(v[i] - rmax); ls += e[i]; }
    sv[t] = ls; __syncthreads();
    for (int off = 64; off; off >>= 1){
        if (t < off) sv[t] += sv[t+off];
        __syncthreads();
    }
    float inv = 1.f/sv[0];
    float* lg = probs + (size_t)row*Oo;
    float* sp = samp + (size_t)row*Oo;
    #pragma unroll
    for (int i = 0; i < 4; ++i){
        int p = t + i*128;
        lg[p] = e[i]*inv;
        sp[p] = (p == ridx) ? 1.f : 0.f;
    }
}

__global__ void k_hxout(float* __restrict__ out){
    int t = blockIdx.x*blockDim.x + threadIdx.x;
    if (t < Bb*Hh) out[t] = g_h[t];
}

// ---------------- launch ----------------
extern "C" void kernel_launch(void* const* d_in, const int* in_sizes, int n_in,
                              void* d_out, int out_size){
    const float* y    = (const float*)d_in[0];
    const float* gt   = (const float*)d_in[1];
    const float* hx   = (const float*)d_in[2];
    const float* Wih  = (const float*)d_in[3];
    const float* bih  = (const float*)d_in[4];
    const float* Whh  = (const float*)d_in[5];
    const float* bhh  = (const float*)d_in[6];
    const float* lw   = (const float*)d_in[7];
    const float* lb   = (const float*)d_in[8];
    const float* gotk = (const float*)d_in[9];
    float* out = (float*)d_out;

    float* out_probs = out;
    float* out_pre   = out + (size_t)16777216;
    float* out_samp  = out + (size_t)50331648;
    float* out_hx    = out + (size_t)67108864;

    static int smem_set = 0;
    if (!smem_set){
        cudaFuncSetAttribute(k_recur, cudaFuncAttributeMaxDynamicSharedMemorySize, 184320);
        smem_set = 1;
    }

    k_idx    <<<RWS/8, 256>>>(gt, gotk);
    k_yT     <<<65536, 256>>>(y);
    k_h0     <<<Bb*Hh/256, 256>>>(hx);
    k_convWhh<<<12288, 256>>>(Whh);
    k_convWih<<<12288, 256>>>(Wih);
    k_convLw <<<2048, 256>>>(lw);
    k_prepT  <<<dim3(96, 16), dim3(32, 8)>>>(Wih);

    k_giW    <<<dim3(24, 256), 256>>>();
    k_giBias <<<98304, 256>>>(bih);

    k_recur  <<<NCTA, 256, 184320>>>(bhh, out_pre);

    k_lwW    <<<dim3(4, 256), 256>>>();
    k_softmax<<<RWS, 128>>>(lb, out_probs, out_samp);
    k_hxout  <<<Bb*Hh/256, 256>>>(out_hx);
}

// round 11
// speedup vs baseline: 1.1242x; 1.1242x over previous
#include <cuda_runtime.h>
#include <cuda_bf16.h>
#include <mma.h>
#include <math.h>
#include <cstdint>

using namespace nvcuda;

#define Bb 128
#define Ss 256
#define Ii 512
#define Oo 512
#define Hh 1024
#define G3 3072
#define RWS (Ss*Bb)

// ---------------- scratch ----------------
__device__ __align__(16) float g_yT[16777216];    // [s*B+b][I]
__device__ int   g_idx[RWS];
__device__ __align__(16) float g_gi[100663296];   // [s*B+b][3H]
__device__ __align__(16) float g_gh4[4*Bb*G3];    // 4 K-split partials
__device__ __align__(16) float g_hs[33685504];    // [(s+1)][B][H]
__device__ __align__(16) float g_hsB[33554432];   // [b*S+s][H]
__device__ __align__(16) float g_lg[16777216];    // raw logits
__device__ __align__(16) float g_WtgtT[Oo*G3];
__device__ __align__(16) __nv_bfloat16 g_hH16[Bb*Hh], g_hL16[Bb*Hh];   // packed h
__device__ __align__(16) __nv_bfloat16 g_WhhHi[G3*1024], g_WhhLo[G3*1024];
__device__ __align__(16) __nv_bfloat16 g_WihHi[G3*1024], g_WihLo[G3*1024];
__device__ __align__(16) __nv_bfloat16 g_LwHi[Oo*1024],  g_LwLo[Oo*1024];

typedef wmma::fragment<wmma::matrix_a, 16,16,16, __nv_bfloat16, wmma::row_major> FragA;
typedef wmma::fragment<wmma::matrix_b, 16,16,16, __nv_bfloat16, wmma::col_major> FragB;
typedef wmma::fragment<wmma::accumulator, 16,16,16, float> FragC;

#define SROW 20
#define SROW_E 40

__device__ __forceinline__ void cvt16(const float4 v0, const float4 v1, uint4& hi, uint4& lo){
    __nv_bfloat16 h0, h1, l0, l1;
    h0=__float2bfloat16(v0.x); h1=__float2bfloat16(v0.y);
    l0=__float2bfloat16(v0.x-__bfloat162float(h0)); l1=__float2bfloat16(v0.y-__bfloat162float(h1));
    hi.x = ((uint32_t)__bfloat16_as_ushort(h1)<<16) | __bfloat16_as_ushort(h0);
    lo.x = ((uint32_t)__bfloat16_as_ushort(l1)<<16) | __bfloat16_as_ushort(l0);
    h0=__float2bfloat16(v0.z); h1=__float2bfloat16(v0.w);
    l0=__float2bfloat16(v0.z-__bfloat162float(h0)); l1=__float2bfloat16(v0.w-__bfloat162float(h1));
    hi.y = ((uint32_t)__bfloat16_as_ushort(h1)<<16) | __bfloat16_as_ushort(h0);
    lo.y = ((uint32_t)__bfloat16_as_ushort(l1)<<16) | __bfloat16_as_ushort(l0);
    h0=__float2bfloat16(v1.x); h1=__float2bfloat16(v1.y);
    l0=__float2bfloat16(v1.x-__bfloat162float(h0)); l1=__float2bfloat16(v1.y-__bfloat162float(h1));
    hi.z = ((uint32_t)__bfloat16_as_ushort(h1)<<16) | __bfloat16_as_ushort(h0);
    lo.z = ((uint32_t)__bfloat16_as_ushort(l1)<<16) | __bfloat16_as_ushort(l0);
    h0=__float2bfloat16(v1.z); h1=__float2bfloat16(v1.w);
    l0=__float2bfloat16(v1.z-__bfloat162float(h0)); l1=__float2bfloat16(v1.w-__bfloat162float(h1));
    hi.w = ((uint32_t)__bfloat16_as_ushort(h1)<<16) | __bfloat16_as_ushort(h0);
    lo.w = ((uint32_t)__bfloat16_as_ushort(l1)<<16) | __bfloat16_as_ushort(l0);
}

// ---------------- shared wmma compute stage ----------------
__device__ __forceinline__ void mma_stage(
    const uint32_t* sAHi, const uint32_t* sALo,
    const uint32_t* sBHi, const uint32_t* sBLo,
    int rowOff, int colOff, FragC acc[2][4])
{
    const __nv_bfloat16* eAh = reinterpret_cast<const __nv_bfloat16*>(sAHi);
    const __nv_bfloat16* eAl = reinterpret_cast<const __nv_bfloat16*>(sALo);
    const __nv_bfloat16* eBh = reinterpret_cast<const __nv_bfloat16*>(sBHi);
    const __nv_bfloat16* eBl = reinterpret_cast<const __nv_bfloat16*>(sBLo);
    #pragma unroll
    for (int ks = 0; ks < 2; ++ks){
        FragA ah[2], al[2];
        #pragma unroll
        for (int mi = 0; mi < 2; ++mi){
            wmma::load_matrix_sync(ah[mi], eAh + (rowOff + mi*16)*SROW_E + ks*16, SROW_E);
            wmma::load_matrix_sync(al[mi], eAl + (rowOff + mi*16)*SROW_E + ks*16, SROW_E);
        }
        #pragma unroll
        for (int ni = 0; ni < 4; ++ni){
            FragB bh, bl;
            wmma::load_matrix_sync(bh, eBh + (colOff + ni*16)*SROW_E + ks*16, SROW_E);
            wmma::load_matrix_sync(bl, eBl + (colOff + ni*16)*SROW_E + ks*16, SROW_E);
            #pragma unroll
            for (int mi = 0; mi < 2; ++mi){
                wmma::mma_sync(acc[mi][ni], ah[mi], bh, acc[mi][ni]);
                wmma::mma_sync(acc[mi][ni], ah[mi], bl, acc[mi][ni]);
                wmma::mma_sync(acc[mi][ni], al[mi], bh, acc[mi][ni]);
            }
        }
    }
}

// copy a 128x32 bf16 tile from global (ld elements) into padded smem
__device__ __forceinline__ void copy_tile16(uint32_t* dst, const __nv_bfloat16* __restrict__ src,
                                            int ld, int rowBase, int k0){
    int t = threadIdx.x;
    #pragma unroll
    for (int it = 0; it < 2; ++it){
        int idx = it*256 + t;
        int row = idx >> 2, seg = idx & 3;
        *reinterpret_cast<uint4*>(dst + row*SROW + seg*4) =
            *reinterpret_cast<const uint4*>(src + (size_t)(rowBase+row)*ld + k0 + seg*8);
    }
}

// ---------------- wmma GEMM, fp32 A converted in-kernel (R7-proven; gi/logits) ----------------
__device__ __forceinline__ void wmma_gemm(
    const float* __restrict__ Asrc, int lda, int mBase,
    const __nv_bfloat16* __restrict__ BHi, const __nv_bfloat16* __restrict__ BLo,
    int ldb, int nBase, int k0, int nChunks,
    float* __restrict__ dst, int ldd)
{
    __shared__ __align__(16) uint32_t sAHi[128*SROW], sALo[128*SROW];
    __shared__ __align__(16) uint32_t sBHi[128*SROW], sBLo[128*SROW];
    int t = threadIdx.x;
    FragC acc[2][4];
    #pragma unroll
    for (int mi = 0; mi < 2; ++mi)
        #pragma unroll
        for (int ni = 0; ni < 4; ++ni) wmma::fill_fragment(acc[mi][ni], 0.f);
    int w = t >> 5;
    int rowOff = (w&3)*32, colOff = (w>>2)*64;
    for (int c = 0; c < nChunks; ++c){
        int kc = k0 + c*32;
        #pragma unroll
        for (int it = 0; it < 2; ++it){
            int idx = it*256 + t;
            int row = idx >> 2, seg = idx & 3;
            const float* p = Asrc + (size_t)(mBase + row)*lda + kc + seg*8;
            float4 v0 = *reinterpret_cast<const float4*>(p);
            float4 v1 = *reinterpret_cast<const float4*>(p + 4);
            uint4 hi, lo; cvt16(v0, v1, hi, lo);
            *reinterpret_cast<uint4*>(sAHi + row*SROW + seg*4) = hi;
            *reinterpret_cast<uint4*>(sALo + row*SROW + seg*4) = lo;
        }
        copy_tile16(sBHi, BHi, ldb, nBase, kc);
        copy_tile16(sBLo, BLo, ldb, nBase, kc);
        __syncthreads();
        mma_stage(sAHi, sALo, sBHi, sBLo, rowOff, colOff, acc);
        __syncthreads();
    }
    #pragma unroll
    for (int mi = 0; mi < 2; ++mi)
        #pragma unroll
        for (int ni = 0; ni < 4; ++ni)
            wmma::store_matrix_sync(dst + (size_t)(mBase + rowOff + mi*16)*ldd
                                        + nBase + colOff + ni*16,
                                    acc[mi][ni], ldd, wmma::mem_row_major);
}

// ---------------- recurrence GEMM, pre-packed bf16 A ----------------
__global__ void __launch_bounds__(256, 1) k_ghB(){
    __shared__ __align__(16) uint32_t sAHi[128*SROW], sALo[128*SROW];
    __shared__ __align__(16) uint32_t sBHi[128*SROW], sBLo[128*SROW];
    int nt = blockIdx.x, kz = blockIdx.y;
    int nBase = nt*128, k0 = kz*256;
    int t = threadIdx.x, w = t >> 5;
    int rowOff = (w&3)*32, colOff = (w>>2)*64;
    FragC acc[2][4];
    #pragma unroll
    for (int mi = 0; mi < 2; ++mi)
        #pragma unroll
        for (int ni = 0; ni < 4; ++ni) wmma::fill_fragment(acc[mi][ni], 0.f);
    for (int c = 0; c < 8; ++c){
        int kc = k0 + c*32;
        copy_tile16(sAHi, g_hH16, 1024, 0, kc);
        copy_tile16(sALo, g_hL16, 1024, 0, kc);
        copy_tile16(sBHi, g_WhhHi, 1024, nBase, kc);
        copy_tile16(sBLo, g_WhhLo, 1024, nBase, kc);
        __syncthreads();
        mma_stage(sAHi, sALo, sBHi, sBLo, rowOff, colOff, acc);
        __syncthreads();
    }
    float* dst = g_gh4 + (size_t)kz*Bb*G3;
    #pragma unroll
    for (int mi = 0; mi < 2; ++mi)
        #pragma unroll
        for (int ni = 0; ni < 4; ++ni)
            wmma::store_matrix_sync(dst + (size_t)(rowOff + mi*16)*G3
                                        + nBase + colOff + ni*16,
                                    acc[mi][ni], G3, wmma::mem_row_major);
}

// ---------------- prep kernels ----------------
__global__ void k_idx(const float* __restrict__ gt, const float* __restrict__ gotoken){
    int w = (blockIdx.x*blockDim.x + threadIdx.x) >> 5;
    int lane = threadIdx.x & 31;
    if (w >= RWS) return;
    int s = w / Bb, b = w % Bb;
    const float* src = (s == 0) ? gotoken : gt + ((size_t)b*Ss + (s-1))*Oo;
    int found = Oo - 1;
    for (int o = lane; o < Oo; o += 32)
        if (src[o] > 0.5f) found = o;
    #pragma unroll
    for (int off = 16; off; off >>= 1)
        found = min(found, __shfl_xor_sync(0xffffffffu, found, off));
    if (lane == 0) g_idx[w] = found;
}

__global__ void k_yT(const float* __restrict__ y){
    size_t t = (size_t)blockIdx.x*blockDim.x + threadIdx.x;
    if (t >= (size_t)RWS*Ii) return;
    int i = (int)(t % Ii); int r = (int)(t / Ii);
    int s = r / Bb, b = r % Bb;
    g_yT[t] = y[((size_t)b*Ss + s)*Ii + i];
}

__global__ void k_h0(const float* __restrict__ hx){
    int t = blockIdx.x*blockDim.x + threadIdx.x;
    if (t < Bb*Hh){
        float v = hx[t];
        g_hs[t] = v;
        __nv_bfloat16 h = __float2bfloat16(v);
        g_hH16[t] = h;
        g_hL16[t] = __float2bfloat16(v - __bfloat162float(h));
    }
}

__global__ void k_convWhh(const float* __restrict__ W){
    int t = blockIdx.x*blockDim.x + threadIdx.x;
    float v = W[t];
    __nv_bfloat16 h = __float2bfloat16(v);
    g_WhhHi[t] = h;
    g_WhhLo[t] = __float2bfloat16(v - __bfloat162float(h));
}
__global__ void k_convWih(const float* __restrict__ W){
    int t = blockIdx.x*blockDim.x + threadIdx.x;
    float v = W[t];
    __nv_bfloat16 h = __float2bfloat16(v);
    g_WihHi[t] = h;
    g_WihLo[t] = __float2bfloat16(v - __bfloat162float(h));
}
__global__ void k_convLw(const float* __restrict__ W){
    int t = blockIdx.x*blockDim.x + threadIdx.x;
    float v = W[t];
    __nv_bfloat16 h = __float2bfloat16(v);
    g_LwHi[t] = h;
    g_LwLo[t] = __float2bfloat16(v - __bfloat162float(h));
}

__global__ void k_prepT(const float* __restrict__ Wih){
    __shared__ float tile[32][33];
    int gB = blockIdx.x*32, oB = blockIdx.y*32;
    int tx = threadIdx.x, ty = threadIdx.y;
    #pragma unroll
    for (int j = 0; j < 32; j += 8)
        tile[ty+j][tx] = Wih[(size_t)(gB + ty + j)*1024 + 512 + oB + tx];
    __syncthreads();
    #pragma unroll
    for (int j = 0; j < 32; j += 8)
        g_WtgtT[(size_t)(oB + ty + j)*3072 + gB + tx] = tile[tx][ty+j];
}

// ---------------- GEMM kernels ----------------
__global__ void __launch_bounds__(256, 1) k_giW(){
    wmma_gemm(g_yT, 512, blockIdx.y*128,
              g_WihHi, g_WihLo, 1024, blockIdx.x*128, 0, 16,
              g_gi, 3072);
}

__global__ void __launch_bounds__(256, 1) k_lwW(){
    wmma_gemm(g_hsB, 1024, blockIdx.y*128,
              g_LwHi, g_LwLo, 1024, blockIdx.x*128, 0, 32,
              g_lg, 512);
}

// gi epilogue: add bih + one-hot gather column (25165824 float4 tasks)
__global__ void k_giBias(const float* __restrict__ bih){
    int idx = blockIdx.x*blockDim.x + threadIdx.x;
    int row = idx / 768;
    int n4 = (idx - row*768)*4;
    int id = g_idx[row];
    float4 v = *reinterpret_cast<float4*>(g_gi + (size_t)row*3072 + n4);
    float4 b = *reinterpret_cast<const float4*>(bih + n4);
    float4 wv = *reinterpret_cast<const float4*>(g_WtgtT + (size_t)id*3072 + n4);
    v.x += b.x + wv.x; v.y += b.y + wv.y; v.z += b.z + wv.z; v.w += b.w + wv.w;
    *reinterpret_cast<float4*>(g_gi + (size_t)row*3072 + n4) = v;
}

// ---------------- gates (R9 + packed-h write) ----------------
__global__ void k_gates(const float* __restrict__ bhh, float* __restrict__ pre_out, int s){
    int t = blockIdx.x*blockDim.x + threadIdx.x;
    if (t >= Bb*Hh) return;
    int b = t >> 10, j = t & 1023;
    size_t gio = ((size_t)s*Bb + b)*G3 + j;
    float i_r = g_gi[gio], i_z = g_gi[gio + Hh], i_n = g_gi[gio + 2*Hh];
    size_t gho = (size_t)b*G3 + j;
    float h_r = bhh[j], h_z = bhh[Hh + j], h_n = bhh[2*Hh + j];
    #pragma unroll
    for (int kz = 0; kz < 4; ++kz){
        size_t o = (size_t)kz*Bb*G3 + gho;
        h_r += g_gh4[o]; h_z += g_gh4[o + Hh]; h_n += g_gh4[o + 2*Hh];
    }
    float rg = 1.f/(1.f + expf(-(i_r + h_r)));
    float zg = 1.f/(1.f + expf(-(i_z + h_z)));
    float pre = i_n + rg*h_n;
    float ng = tanhf(pre);
    float hp = g_hs[((size_t)s*Bb + b)*Hh + j];
    float hy = ng + zg*(hp - ng);
    g_hs [((size_t)(s+1)*Bb + b)*Hh + j] = hy;
    g_hsB[((size_t)b*Ss + s)*Hh + j]     = hy;
    pre_out[((size_t)b*Ss + s)*Hh + j]   = pre;
    __nv_bfloat16 hh = __float2bfloat16(hy);
    g_hH16[t] = hh;
    g_hL16[t] = __float2bfloat16(hy - __bfloat162float(hh));
}

// ---------------- softmax + argmax ----------------
__global__ void k_softmax(const float* __restrict__ lb,
                          float* __restrict__ probs, float* __restrict__ samp){
    __shared__ float sv[128];
    __shared__ int   si[128];
    int row = blockIdx.x;
    int t = threadIdx.x;
    const float* lgi = g_lg + (size_t)row*Oo;
    float v[4];
    #pragma unroll
    for (int i = 0; i < 4; ++i) v[i] = lgi[t + i*128] + lb[t + i*128];
    float lmax = v[0]; int lidx = t;
    #pragma unroll
    for (int i = 1; i < 4; ++i)
        if (v[i] > lmax){ lmax = v[i]; lidx = t + i*128; }
    sv[t] = lmax; si[t] = lidx; __syncthreads();
    for (int off = 64; off; off >>= 1){
        if (t < off){
            float v2 = sv[t+off]; int i2 = si[t+off];
            if (v2 > sv[t] || (v2 == sv[t] && i2 < si[t])){ sv[t] = v2; si[t] = i2; }
        }
        __syncthreads();
    }
    float rmax = sv[0]; int ridx = si[0];
    __syncthreads();
    float e[4]; float ls = 0.f;
    #pragma unroll
    for (int i = 0; i < 4; ++i){ e[i] = expf(v[i] - rmax); ls += e[i]; }
    sv[t] = ls; __syncthreads();
    for (int off = 64; off; off >>= 1){
        if (t < off) sv[t] += sv[t+off];
        __syncthreads();
    }
    float inv = 1.f/sv[0];
    float* lg = probs + (size_t)row*Oo;
    float* sp = samp + (size_t)row*Oo;
    #pragma unroll
    for (int i = 0; i < 4; ++i){
        int p = t + i*128;
        lg[p] = e[i]*inv;
        sp[p] = (p == ridx) ? 1.f : 0.f;
    }
}

__global__ void k_hxout(float* __restrict__ out){
    int t = blockIdx.x*blockDim.x + threadIdx.x;
    if (t < Bb*Hh) out[t] = g_hs[(size_t)Ss*Bb*Hh + t];
}

// ---------------- launch ----------------
extern "C" void kernel_launch(void* const* d_in, const int* in_sizes, int n_in,
                              void* d_out, int out_size){
    const float* y    = (const float*)d_in[0];
    const float* gt   = (const float*)d_in[1];
    const float* hx   = (const float*)d_in[2];
    const float* Wih  = (const float*)d_in[3];
    const float* bih  = (const float*)d_in[4];
    const float* Whh  = (const float*)d_in[5];
    const float* bhh  = (const float*)d_in[6];
    const float* lw   = (const float*)d_in[7];
    const float* lb   = (const float*)d_in[8];
    const float* gotk = (const float*)d_in[9];
    float* out = (float*)d_out;

    float* out_probs = out;
    float* out_pre   = out + (size_t)16777216;
    float* out_samp  = out + (size_t)50331648;
    float* out_hx    = out + (size_t)67108864;

    k_idx    <<<RWS/8, 256>>>(gt, gotk);
    k_yT     <<<65536, 256>>>(y);
    k_h0     <<<Bb*Hh/256, 256>>>(hx);
    k_convWhh<<<12288, 256>>>(Whh);
    k_convWih<<<12288, 256>>>(Wih);
    k_convLw <<<2048, 256>>>(lw);
    k_prepT  <<<dim3(96, 16), dim3(32, 8)>>>(Wih);

    k_giW    <<<dim3(24, 256), 256>>>();
    k_giBias <<<98304, 256>>>(bih);

    for (int s = 0; s < Ss; ++s){
        k_ghB  <<<dim3(24, 4), 256>>>();
        k_gates<<<Bb*Hh/256, 256>>>(bhh, out_pre, s);
    }

    k_lwW    <<<dim3(4, 256), 256>>>();
    k_softmax<<<RWS, 128>>>(lb, out_probs, out_samp);
    k_hxout  <<<Bb*Hh/256, 256>>>(out_hx);
}

// round 12
// speedup vs baseline: 1.2340x; 1.0977x over previous
#include <cuda_runtime.h>
#include <cuda_bf16.h>
#include <mma.h>
#include <math.h>
#include <cstdint>

using namespace nvcuda;

#define Bb 128
#define Ss 256
#define Ii 512
#define Oo 512
#define Hh 1024
#define G3 3072
#define RWS (Ss*Bb)

// ---------------- scratch ----------------
__device__ __align__(16) float g_yT[16777216];    // [s*B+b][I]
__device__ int   g_idx[RWS];
__device__ __align__(16) float g_gi[100663296];   // [s*B+b][3H]
__device__ __align__(16) float g_gh4[4*Bb*G3];    // 4 K-split partials
__device__ __align__(16) float g_hs[33685504];    // [(s+1)][B][H]
__device__ __align__(16) float g_hsB[33554432];   // [b*S+s][H]
__device__ __align__(16) float g_lg[16777216];    // raw logits
__device__ __align__(16) float g_WtgtT[Oo*G3];
__device__ __align__(16) __nv_bfloat16 g_hH16[Bb*Hh], g_hL16[Bb*Hh];   // packed h
__device__ __align__(16) __nv_bfloat16 g_WhhHi[G3*1024], g_WhhLo[G3*1024];
__device__ __align__(16) __nv_bfloat16 g_WihHi[G3*1024], g_WihLo[G3*1024];
__device__ __align__(16) __nv_bfloat16 g_LwHi[Oo*1024],  g_LwLo[Oo*1024];

typedef wmma::fragment<wmma::matrix_a, 16,16,16, __nv_bfloat16, wmma::row_major> FragA;
typedef wmma::fragment<wmma::matrix_b, 16,16,16, __nv_bfloat16, wmma::col_major> FragB;
typedef wmma::fragment<wmma::accumulator, 16,16,16, float> FragC;

#define SROW 20
#define SROW_E 40
#define STG 10240   // u32 words per pipeline stage (4 tiles x 2560)

__device__ __forceinline__ void cvt16(const float4 v0, const float4 v1, uint4& hi, uint4& lo){
    __nv_bfloat16 h0, h1, l0, l1;
    h0=__float2bfloat16(v0.x); h1=__float2bfloat16(v0.y);
    l0=__float2bfloat16(v0.x-__bfloat162float(h0)); l1=__float2bfloat16(v0.y-__bfloat162float(h1));
    hi.x = ((uint32_t)__bfloat16_as_ushort(h1)<<16) | __bfloat16_as_ushort(h0);
    lo.x = ((uint32_t)__bfloat16_as_ushort(l1)<<16) | __bfloat16_as_ushort(l0);
    h0=__float2bfloat16(v0.z); h1=__float2bfloat16(v0.w);
    l0=__float2bfloat16(v0.z-__bfloat162float(h0)); l1=__float2bfloat16(v0.w-__bfloat162float(h1));
    hi.y = ((uint32_t)__bfloat16_as_ushort(h1)<<16) | __bfloat16_as_ushort(h0);
    lo.y = ((uint32_t)__bfloat16_as_ushort(l1)<<16) | __bfloat16_as_ushort(l0);
    h0=__float2bfloat16(v1.x); h1=__float2bfloat16(v1.y);
    l0=__float2bfloat16(v1.x-__bfloat162float(h0)); l1=__float2bfloat16(v1.y-__bfloat162float(h1));
    hi.z = ((uint32_t)__bfloat16_as_ushort(h1)<<16) | __bfloat16_as_ushort(h0);
    lo.z = ((uint32_t)__bfloat16_as_ushort(l1)<<16) | __bfloat16_as_ushort(l0);
    h0=__float2bfloat16(v1.z); h1=__float2bfloat16(v1.w);
    l0=__float2bfloat16(v1.z-__bfloat162float(h0)); l1=__float2bfloat16(v1.w-__bfloat162float(h1));
    hi.w = ((uint32_t)__bfloat16_as_ushort(h1)<<16) | __bfloat16_as_ushort(h0);
    lo.w = ((uint32_t)__bfloat16_as_ushort(l1)<<16) | __bfloat16_as_ushort(l0);
}

// ---------------- shared wmma compute stage ----------------
__device__ __forceinline__ void mma_stage(
    const uint32_t* sAHi, const uint32_t* sALo,
    const uint32_t* sBHi, const uint32_t* sBLo,
    int rowOff, int colOff, FragC acc[2][4])
{
    const __nv_bfloat16* eAh = reinterpret_cast<const __nv_bfloat16*>(sAHi);
    const __nv_bfloat16* eAl = reinterpret_cast<const __nv_bfloat16*>(sALo);
    const __nv_bfloat16* eBh = reinterpret_cast<const __nv_bfloat16*>(sBHi);
    const __nv_bfloat16* eBl = reinterpret_cast<const __nv_bfloat16*>(sBLo);
    #pragma unroll
    for (int ks = 0; ks < 2; ++ks){
        FragA ah[2], al[2];
        #pragma unroll
        for (int mi = 0; mi < 2; ++mi){
            wmma::load_matrix_sync(ah[mi], eAh + (rowOff + mi*16)*SROW_E + ks*16, SROW_E);
            wmma::load_matrix_sync(al[mi], eAl + (rowOff + mi*16)*SROW_E + ks*16, SROW_E);
        }
        #pragma unroll
        for (int ni = 0; ni < 4; ++ni){
            FragB bh, bl;
            wmma::load_matrix_sync(bh, eBh + (colOff + ni*16)*SROW_E + ks*16, SROW_E);
            wmma::load_matrix_sync(bl, eBl + (colOff + ni*16)*SROW_E + ks*16, SROW_E);
            #pragma unroll
            for (int mi = 0; mi < 2; ++mi){
                wmma::mma_sync(acc[mi][ni], ah[mi], bh, acc[mi][ni]);
                wmma::mma_sync(acc[mi][ni], ah[mi], bl, acc[mi][ni]);
                wmma::mma_sync(acc[mi][ni], al[mi], bh, acc[mi][ni]);
            }
        }
    }
}

// copy a 128x32 bf16 tile from global (ld elements) into padded smem
__device__ __forceinline__ void copy_tile16(uint32_t* dst, const __nv_bfloat16* __restrict__ src,
                                            int ld, int rowBase, int k0){
    int t = threadIdx.x;
    #pragma unroll
    for (int it = 0; it < 2; ++it){
        int idx = it*256 + t;
        int row = idx >> 2, seg = idx & 3;
        *reinterpret_cast<uint4*>(dst + row*SROW + seg*4) =
            *reinterpret_cast<const uint4*>(src + (size_t)(rowBase+row)*ld + k0 + seg*8);
    }
}

// ---------------- wmma GEMM, fp32 A converted in-kernel (gi/logits) ----------------
__device__ __forceinline__ void wmma_gemm(
    const float* __restrict__ Asrc, int lda, int mBase,
    const __nv_bfloat16* __restrict__ BHi, const __nv_bfloat16* __restrict__ BLo,
    int ldb, int nBase, int k0, int nChunks,
    float* __restrict__ dst, int ldd)
{
    __shared__ __align__(16) uint32_t sAHi[128*SROW], sALo[128*SROW];
    __shared__ __align__(16) uint32_t sBHi[128*SROW], sBLo[128*SROW];
    int t = threadIdx.x;
    FragC acc[2][4];
    #pragma unroll
    for (int mi = 0; mi < 2; ++mi)
        #pragma unroll
        for (int ni = 0; ni < 4; ++ni) wmma::fill_fragment(acc[mi][ni], 0.f);
    int w = t >> 5;
    int rowOff = (w&3)*32, colOff = (w>>2)*64;
    for (int c = 0; c < nChunks; ++c){
        int kc = k0 + c*32;
        #pragma unroll
        for (int it = 0; it < 2; ++it){
            int idx = it*256 + t;
            int row = idx >> 2, seg = idx & 3;
            const float* p = Asrc + (size_t)(mBase + row)*lda + kc + seg*8;
            float4 v0 = *reinterpret_cast<const float4*>(p);
            float4 v1 = *reinterpret_cast<const float4*>(p + 4);
            uint4 hi, lo; cvt16(v0, v1, hi, lo);
            *reinterpret_cast<uint4*>(sAHi + row*SROW + seg*4) = hi;
            *reinterpret_cast<uint4*>(sALo + row*SROW + seg*4) = lo;
        }
        copy_tile16(sBHi, BHi, ldb, nBase, kc);
        copy_tile16(sBLo, BLo, ldb, nBase, kc);
        __syncthreads();
        mma_stage(sAHi, sALo, sBHi, sBLo, rowOff, colOff, acc);
        __syncthreads();
    }
    #pragma unroll
    for (int mi = 0; mi < 2; ++mi)
        #pragma unroll
        for (int ni = 0; ni < 4; ++ni)
            wmma::store_matrix_sync(dst + (size_t)(mBase + rowOff + mi*16)*ldd
                                        + nBase + colOff + ni*16,
                                    acc[mi][ni], ldd, wmma::mem_row_major);
}

// ---------------- recurrence GEMM: pre-packed bf16 A, 2-stage smem pipeline ----------------
__global__ void __launch_bounds__(256, 1) k_ghB(){
    extern __shared__ __align__(16) uint32_t smb[];   // 2 stages x 40KB
    int nt = blockIdx.x, kz = blockIdx.y;
    int nBase = nt*128, k0 = kz*256;
    int t = threadIdx.x, w = t >> 5;
    int rowOff = (w&3)*32, colOff = (w>>2)*64;
    // per-thread copy coordinates (2 segments per tile)
    int i0 = t, i1 = 256 + t;
    int r0 = i0 >> 2, s0 = i0 & 3;
    int r1 = i1 >> 2, s1 = i1 & 3;
    size_t a0 = (size_t)r0*1024 + s0*8,          a1 = (size_t)r1*1024 + s1*8;
    size_t b0 = (size_t)(nBase+r0)*1024 + s0*8,  b1 = (size_t)(nBase+r1)*1024 + s1*8;
    int d0 = r0*SROW + s0*4, d1 = r1*SROW + s1*4;

    FragC acc[2][4];
    #pragma unroll
    for (int mi = 0; mi < 2; ++mi)
        #pragma unroll
        for (int ni = 0; ni < 4; ++ni) wmma::fill_fragment(acc[mi][ni], 0.f);

    // prologue: chunk 0 -> stage 0
    {
        int kc = k0;
        uint32_t* st = smb;
        *reinterpret_cast<uint4*>(st + d0)        = *reinterpret_cast<const uint4*>(g_hH16 + a0 + kc);
        *reinterpret_cast<uint4*>(st + d1)        = *reinterpret_cast<const uint4*>(g_hH16 + a1 + kc);
        *reinterpret_cast<uint4*>(st + 2560 + d0) = *reinterpret_cast<const uint4*>(g_hL16 + a0 + kc);
        *reinterpret_cast<uint4*>(st + 2560 + d1) = *reinterpret_cast<const uint4*>(g_hL16 + a1 + kc);
        *reinterpret_cast<uint4*>(st + 5120 + d0) = *reinterpret_cast<const uint4*>(g_WhhHi + b0 + kc);
        *reinterpret_cast<uint4*>(st + 5120 + d1) = *reinterpret_cast<const uint4*>(g_WhhHi + b1 + kc);
        *reinterpret_cast<uint4*>(st + 7680 + d0) = *reinterpret_cast<const uint4*>(g_WhhLo + b0 + kc);
        *reinterpret_cast<uint4*>(st + 7680 + d1) = *reinterpret_cast<const uint4*>(g_WhhLo + b1 + kc);
    }
    __syncthreads();

    #pragma unroll
    for (int c = 0; c < 8; ++c){
        uint4 rAh0, rAh1, rAl0, rAl1, rBh0, rBh1, rBl0, rBl1;
        if (c < 7){
            int kc = k0 + (c+1)*32;
            rAh0 = *reinterpret_cast<const uint4*>(g_hH16 + a0 + kc);
            rAh1 = *reinterpret_cast<const uint4*>(g_hH16 + a1 + kc);
            rAl0 = *reinterpret_cast<const uint4*>(g_hL16 + a0 + kc);
            rAl1 = *reinterpret_cast<const uint4*>(g_hL16 + a1 + kc);
            rBh0 = *reinterpret_cast<const uint4*>(g_WhhHi + b0 + kc);
            rBh1 = *reinterpret_cast<const uint4*>(g_WhhHi + b1 + kc);
            rBl0 = *reinterpret_cast<const uint4*>(g_WhhLo + b0 + kc);
            rBl1 = *reinterpret_cast<const uint4*>(g_WhhLo + b1 + kc);
        }
        const uint32_t* st = smb + (c & 1)*STG;
        mma_stage(st, st + 2560, st + 5120, st + 7680, rowOff, colOff, acc);
        if (c < 7){
            uint32_t* dt = smb + ((c+1) & 1)*STG;
            *reinterpret_cast<uint4*>(dt + d0)        = rAh0;
            *reinterpret_cast<uint4*>(dt + d1)        = rAh1;
            *reinterpret_cast<uint4*>(dt + 2560 + d0) = rAl0;
            *reinterpret_cast<uint4*>(dt + 2560 + d1) = rAl1;
            *reinterpret_cast<uint4*>(dt + 5120 + d0) = rBh0;
            *reinterpret_cast<uint4*>(dt + 5120 + d1) = rBh1;
            *reinterpret_cast<uint4*>(dt + 7680 + d0) = rBl0;
            *reinterpret_cast<uint4*>(dt + 7680 + d1) = rBl1;
        }
        __syncthreads();
    }
    float* dst = g_gh4 + (size_t)kz*Bb*G3;
    #pragma unroll
    for (int mi = 0; mi < 2; ++mi)
        #pragma unroll
        for (int ni = 0; ni < 4; ++ni)
            wmma::store_matrix_sync(dst + (size_t)(rowOff + mi*16)*G3
                                        + nBase + colOff + ni*16,
                                    acc[mi][ni], G3, wmma::mem_row_major);
}

// ---------------- prep kernels ----------------
__global__ void k_idx(const float* __restrict__ gt, const float* __restrict__ gotoken){
    int w = (blockIdx.x*blockDim.x + threadIdx.x) >> 5;
    int lane = threadIdx.x & 31;
    if (w >= RWS) return;
    int s = w / Bb, b = w % Bb;
    const float* src = (s == 0) ? gotoken : gt + ((size_t)b*Ss + (s-1))*Oo;
    int found = Oo - 1;
    for (int o = lane; o < Oo; o += 32)
        if (src[o] > 0.5f) found = o;
    #pragma unroll
    for (int off = 16; off; off >>= 1)
        found = min(found, __shfl_xor_sync(0xffffffffu, found, off));
    if (lane == 0) g_idx[w] = found;
}

__global__ void k_yT(const float* __restrict__ y){
    size_t t = (size_t)blockIdx.x*blockDim.x + threadIdx.x;
    if (t >= (size_t)RWS*Ii) return;
    int i = (int)(t % Ii); int r = (int)(t / Ii);
    int s = r / Bb, b = r % Bb;
    g_yT[t] = y[((size_t)b*Ss + s)*Ii + i];
}

__global__ void k_h0(const float* __restrict__ hx){
    int t = blockIdx.x*blockDim.x + threadIdx.x;
    if (t < Bb*Hh){
        float v = hx[t];
        g_hs[t] = v;
        __nv_bfloat16 h = __float2bfloat16(v);
        g_hH16[t] = h;
        g_hL16[t] = __float2bfloat16(v - __bfloat162float(h));
    }
}

__global__ void k_convWhh(const float* __restrict__ W){
    int t = blockIdx.x*blockDim.x + threadIdx.x;
    float v = W[t];
    __nv_bfloat16 h = __float2bfloat16(v);
    g_WhhHi[t] = h;
    g_WhhLo[t] = __float2bfloat16(v - __bfloat162float(h));
}
__global__ void k_convWih(const float* __restrict__ W){
    int t = blockIdx.x*blockDim.x + threadIdx.x;
    float v = W[t];
    __nv_bfloat16 h = __float2bfloat16(v);
    g_WihHi[t] = h;
    g_WihLo[t] = __float2bfloat16(v - __bfloat162float(h));
}
__global__ void k_convLw(const float* __restrict__ W){
    int t = blockIdx.x*blockDim.x + threadIdx.x;
    float v = W[t];
    __nv_bfloat16 h = __float2bfloat16(v);
    g_LwHi[t] = h;
    g_LwLo[t] = __float2bfloat16(v - __bfloat162float(h));
}

__global__ void k_prepT(const float* __restrict__ Wih){
    __shared__ float tile[32][33];
    int gB = blockIdx.x*32, oB = blockIdx.y*32;
    int tx = threadIdx.x, ty = threadIdx.y;
    #pragma unroll
    for (int j = 0; j < 32; j += 8)
        tile[ty+j][tx] = Wih[(size_t)(gB + ty + j)*1024 + 512 + oB + tx];
    __syncthreads();
    #pragma unroll
    for (int j = 0; j < 32; j += 8)
        g_WtgtT[(size_t)(oB + ty + j)*3072 + gB + tx] = tile[tx][ty+j];
}

// ---------------- GEMM kernels ----------------
__global__ void __launch_bounds__(256, 1) k_giW(){
    wmma_gemm(g_yT, 512, blockIdx.y*128,
              g_WihHi, g_WihLo, 1024, blockIdx.x*128, 0, 16,
              g_gi, 3072);
}

__global__ void __launch_bounds__(256, 1) k_lwW(){
    wmma_gemm(g_hsB, 1024, blockIdx.y*128,
              g_LwHi, g_LwLo, 1024, blockIdx.x*128, 0, 32,
              g_lg, 512);
}

// gi epilogue: add bih + one-hot gather column (25165824 float4 tasks)
__global__ void k_giBias(const float* __restrict__ bih){
    int idx = blockIdx.x*blockDim.x + threadIdx.x;
    int row = idx / 768;
    int n4 = (idx - row*768)*4;
    int id = g_idx[row];
    float4 v = *reinterpret_cast<float4*>(g_gi + (size_t)row*3072 + n4);
    float4 b = *reinterpret_cast<const float4*>(bih + n4);
    float4 wv = *reinterpret_cast<const float4*>(g_WtgtT + (size_t)id*3072 + n4);
    v.x += b.x + wv.x; v.y += b.y + wv.y; v.z += b.z + wv.z; v.w += b.w + wv.w;
    *reinterpret_cast<float4*>(g_gi + (size_t)row*3072 + n4) = v;
}

// ---------------- gates ----------------
__global__ void k_gates(const float* __restrict__ bhh, float* __restrict__ pre_out, int s){
    int t = blockIdx.x*blockDim.x + threadIdx.x;
    if (t >= Bb*Hh) return;
    int b = t >> 10, j = t & 1023;
    size_t gio = ((size_t)s*Bb + b)*G3 + j;
    float i_r = g_gi[gio], i_z = g_gi[gio + Hh], i_n = g_gi[gio + 2*Hh];
    size_t gho = (size_t)b*G3 + j;
    float h_r = bhh[j], h_z = bhh[Hh + j], h_n = bhh[2*Hh + j];
    #pragma unroll
    for (int kz = 0; kz < 4; ++kz){
        size_t o = (size_t)kz*Bb*G3 + gho;
        h_r += g_gh4[o]; h_z += g_gh4[o + Hh]; h_n += g_gh4[o + 2*Hh];
    }
    float rg = 1.f/(1.f + expf(-(i_r + h_r)));
    float zg = 1.f/(1.f + expf(-(i_z + h_z)));
    float pre = i_n + rg*h_n;
    float ng = tanhf(pre);
    float hp = g_hs[((size_t)s*Bb + b)*Hh + j];
    float hy = ng + zg*(hp - ng);
    g_hs [((size_t)(s+1)*Bb + b)*Hh + j] = hy;
    g_hsB[((size_t)b*Ss + s)*Hh + j]     = hy;
    pre_out[((size_t)b*Ss + s)*Hh + j]   = pre;
    __nv_bfloat16 hh = __float2bfloat16(hy);
    g_hH16[t] = hh;
    g_hL16[t] = __float2bfloat16(hy - __bfloat162float(hh));
}

// ---------------- softmax + argmax ----------------
__global__ void k_softmax(const float* __restrict__ lb,
                          float* __restrict__ probs, float* __restrict__ samp){
    __shared__ float sv[128];
    __shared__ int   si[128];
    int row = blockIdx.x;
    int t = threadIdx.x;
    const float* lgi = g_lg + (size_t)row*Oo;
    float v[4];
    #pragma unroll
    for (int i = 0; i < 4; ++i) v[i] = lgi[t + i*128] + lb[t + i*128];
    float lmax = v[0]; int lidx = t;
    #pragma unroll
    for (int i = 1; i < 4; ++i)
        if (v[i] > lmax){ lmax = v[i]; lidx = t + i*128; }
    sv[t] = lmax; si[t] = lidx; __syncthreads();
    for (int off = 64; off; off >>= 1){
        if (t < off){
            float v2 = sv[t+off]; int i2 = si[t+off];
            if (v2 > sv[t] || (v2 == sv[t] && i2 < si[t])){ sv[t] = v2; si[t] = i2; }
        }
        __syncthreads();
    }
    float rmax = sv[0]; int ridx = si[0];
    __syncthreads();
    float e[4]; float ls = 0.f;
    #pragma unroll
    for (int i = 0; i < 4; ++i){ e[i] = expf(v[i] - rmax); ls += e[i]; }
    sv[t] = ls; __syncthreads();
    for (int off = 64; off; off >>= 1){
        if (t < off) sv[t] += sv[t+off];
        __syncthreads();
    }
    float inv = 1.f/sv[0];
    float* lg = probs + (size_t)row*Oo;
    float* sp = samp + (size_t)row*Oo;
    #pragma unroll
    for (int i = 0; i < 4; ++i){
        int p = t + i*128;
        lg[p] = e[i]*inv;
        sp[p] = (p == ridx) ? 1.f : 0.f;
    }
}

__global__ void k_hxout(float* __restrict__ out){
    int t = blockIdx.x*blockDim.x + threadIdx.x;
    if (t < Bb*Hh) out[t] = g_hs[(size_t)Ss*Bb*Hh + t];
}

// ---------------- launch ----------------
extern "C" void kernel_launch(void* const* d_in, const int* in_sizes, int n_in,
                              void* d_out, int out_size){
    const float* y    = (const float*)d_in[0];
    const float* gt   = (const float*)d_in[1];
    const float* hx   = (const float*)d_in[2];
    const float* Wih  = (const float*)d_in[3];
    const float* bih  = (const float*)d_in[4];
    const float* Whh  = (const float*)d_in[5];
    const float* bhh  = (const float*)d_in[6];
    const float* lw   = (const float*)d_in[7];
    const float* lb   = (const float*)d_in[8];
    const float* gotk = (const float*)d_in[9];
    float* out = (float*)d_out;

    float* out_probs = out;
    float* out_pre   = out + (size_t)16777216;
    float* out_samp  = out + (size_t)50331648;
    float* out_hx    = out + (size_t)67108864;

    static int attr_set = 0;
    if (!attr_set){
        cudaFuncSetAttribute(k_ghB, cudaFuncAttributeMaxDynamicSharedMemorySize, 81920);
        attr_set = 1;
    }

    k_idx    <<<RWS/8, 256>>>(gt, gotk);
    k_yT     <<<65536, 256>>>(y);
    k_h0     <<<Bb*Hh/256, 256>>>(hx);
    k_convWhh<<<12288, 256>>>(Whh);
    k_convWih<<<12288, 256>>>(Wih);
    k_convLw <<<2048, 256>>>(lw);
    k_prepT  <<<dim3(96, 16), dim3(32, 8)>>>(Wih);

    k_giW    <<<dim3(24, 256), 256>>>();
    k_giBias <<<98304, 256>>>(bih);

    for (int s = 0; s < Ss; ++s){
        k_ghB  <<<dim3(24, 4), 256, 81920>>>();
        k_gates<<<Bb*Hh/256, 256>>>(bhh, out_pre, s);
    }

    k_lwW    <<<dim3(4, 256), 256>>>();
    k_softmax<<<RWS, 128>>>(lb, out_probs, out_samp);
    k_hxout  <<<Bb*Hh/256, 256>>>(out_hx);
}

// round 13
// speedup vs baseline: 1.3944x; 1.1300x over previous
#include <cuda_runtime.h>
#include <cuda_bf16.h>
#include <mma.h>
#include <math.h>
#include <cstdint>

using namespace nvcuda;

#define Bb 128
#define Ss 256
#define Ii 512
#define Oo 512
#define Hh 1024
#define G3 3072
#define RWS (Ss*Bb)

// ---------------- scratch ----------------
__device__ __align__(16) float g_yT[16777216];    // [s*B+b][I]
__device__ int   g_idx[RWS];
__device__ __align__(16) float g_gi[100663296];   // [s*B+b][3H]
__device__ __align__(16) float g_gh4[4*Bb*G3];    // 4 K-split partials
__device__ __align__(16) float g_hs[33685504];    // [(s+1)][B][H]
__device__ __align__(16) float g_hsB[33554432];   // [b*S+s][H]
__device__ __align__(16) float g_lg[16777216];    // raw logits
__device__ __align__(16) float g_WtgtT[Oo*G3];
__device__ __align__(16) __nv_bfloat16 g_hH16[Bb*Hh], g_hL16[Bb*Hh];   // packed h
__device__ __align__(16) __nv_bfloat16 g_WhhHi[G3*1024], g_WhhLo[G3*1024];
__device__ __align__(16) __nv_bfloat16 g_WihHi[G3*1024], g_WihLo[G3*1024];
__device__ __align__(16) __nv_bfloat16 g_LwHi[Oo*1024],  g_LwLo[Oo*1024];

typedef wmma::fragment<wmma::matrix_a, 16,16,16, __nv_bfloat16, wmma::row_major> FragA;
typedef wmma::fragment<wmma::matrix_b, 16,16,16, __nv_bfloat16, wmma::col_major> FragB;
typedef wmma::fragment<wmma::accumulator, 16,16,16, float> FragC;

#define SROW 20
#define SROW_E 40
// k_ghB stage layout (u32 words): AHi 0, ALo 2560, BHi 5120, BLo 7040; stage = 8960
#define STG96 8960

__device__ __forceinline__ void cvt16(const float4 v0, const float4 v1, uint4& hi, uint4& lo){
    __nv_bfloat16 h0, h1, l0, l1;
    h0=__float2bfloat16(v0.x); h1=__float2bfloat16(v0.y);
    l0=__float2bfloat16(v0.x-__bfloat162float(h0)); l1=__float2bfloat16(v0.y-__bfloat162float(h1));
    hi.x = ((uint32_t)__bfloat16_as_ushort(h1)<<16) | __bfloat16_as_ushort(h0);
    lo.x = ((uint32_t)__bfloat16_as_ushort(l1)<<16) | __bfloat16_as_ushort(l0);
    h0=__float2bfloat16(v0.z); h1=__float2bfloat16(v0.w);
    l0=__float2bfloat16(v0.z-__bfloat162float(h0)); l1=__float2bfloat16(v0.w-__bfloat162float(h1));
    hi.y = ((uint32_t)__bfloat16_as_ushort(h1)<<16) | __bfloat16_as_ushort(h0);
    lo.y = ((uint32_t)__bfloat16_as_ushort(l1)<<16) | __bfloat16_as_ushort(l0);
    h0=__float2bfloat16(v1.x); h1=__float2bfloat16(v1.y);
    l0=__float2bfloat16(v1.x-__bfloat162float(h0)); l1=__float2bfloat16(v1.y-__bfloat162float(h1));
    hi.z = ((uint32_t)__bfloat16_as_ushort(h1)<<16) | __bfloat16_as_ushort(h0);
    lo.z = ((uint32_t)__bfloat16_as_ushort(l1)<<16) | __bfloat16_as_ushort(l0);
    h0=__float2bfloat16(v1.z); h1=__float2bfloat16(v1.w);
    l0=__float2bfloat16(v1.z-__bfloat162float(h0)); l1=__float2bfloat16(v1.w-__bfloat162float(h1));
    hi.w = ((uint32_t)__bfloat16_as_ushort(h1)<<16) | __bfloat16_as_ushort(h0);
    lo.w = ((uint32_t)__bfloat16_as_ushort(l1)<<16) | __bfloat16_as_ushort(l0);
}

// ---------------- wmma compute stage, 128-wide C (gi/logits) ----------------
__device__ __forceinline__ void mma_stage(
    const uint32_t* sAHi, const uint32_t* sALo,
    const uint32_t* sBHi, const uint32_t* sBLo,
    int rowOff, int colOff, FragC acc[2][4])
{
    const __nv_bfloat16* eAh = reinterpret_cast<const __nv_bfloat16*>(sAHi);
    const __nv_bfloat16* eAl = reinterpret_cast<const __nv_bfloat16*>(sALo);
    const __nv_bfloat16* eBh = reinterpret_cast<const __nv_bfloat16*>(sBHi);
    const __nv_bfloat16* eBl = reinterpret_cast<const __nv_bfloat16*>(sBLo);
    #pragma unroll
    for (int ks = 0; ks < 2; ++ks){
        FragA ah[2], al[2];
        #pragma unroll
        for (int mi = 0; mi < 2; ++mi){
            wmma::load_matrix_sync(ah[mi], eAh + (rowOff + mi*16)*SROW_E + ks*16, SROW_E);
            wmma::load_matrix_sync(al[mi], eAl + (rowOff + mi*16)*SROW_E + ks*16, SROW_E);
        }
        #pragma unroll
        for (int ni = 0; ni < 4; ++ni){
            FragB bh, bl;
            wmma::load_matrix_sync(bh, eBh + (colOff + ni*16)*SROW_E + ks*16, SROW_E);
            wmma::load_matrix_sync(bl, eBl + (colOff + ni*16)*SROW_E + ks*16, SROW_E);
            #pragma unroll
            for (int mi = 0; mi < 2; ++mi){
                wmma::mma_sync(acc[mi][ni], ah[mi], bh, acc[mi][ni]);
                wmma::mma_sync(acc[mi][ni], ah[mi], bl, acc[mi][ni]);
                wmma::mma_sync(acc[mi][ni], al[mi], bh, acc[mi][ni]);
            }
        }
    }
}

// ---------------- wmma compute stage, 96-wide C (recurrence) ----------------
__device__ __forceinline__ void mma_stage96(
    const uint32_t* sAHi, const uint32_t* sALo,
    const uint32_t* sBHi, const uint32_t* sBLo,
    int rowOff, int colOff, FragC acc[2][3])
{
    const __nv_bfloat16* eAh = reinterpret_cast<const __nv_bfloat16*>(sAHi);
    const __nv_bfloat16* eAl = reinterpret_cast<const __nv_bfloat16*>(sALo);
    const __nv_bfloat16* eBh = reinterpret_cast<const __nv_bfloat16*>(sBHi);
    const __nv_bfloat16* eBl = reinterpret_cast<const __nv_bfloat16*>(sBLo);
    #pragma unroll
    for (int ks = 0; ks < 2; ++ks){
        FragA ah[2], al[2];
        #pragma unroll
        for (int mi = 0; mi < 2; ++mi){
            wmma::load_matrix_sync(ah[mi], eAh + (rowOff + mi*16)*SROW_E + ks*16, SROW_E);
            wmma::load_matrix_sync(al[mi], eAl + (rowOff + mi*16)*SROW_E + ks*16, SROW_E);
        }
        #pragma unroll
        for (int ni = 0; ni < 3; ++ni){
            FragB bh, bl;
            wmma::load_matrix_sync(bh, eBh + (colOff + ni*16)*SROW_E + ks*16, SROW_E);
            wmma::load_matrix_sync(bl, eBl + (colOff + ni*16)*SROW_E + ks*16, SROW_E);
            #pragma unroll
            for (int mi = 0; mi < 2; ++mi){
                wmma::mma_sync(acc[mi][ni], ah[mi], bh, acc[mi][ni]);
                wmma::mma_sync(acc[mi][ni], ah[mi], bl, acc[mi][ni]);
                wmma::mma_sync(acc[mi][ni], al[mi], bh, acc[mi][ni]);
            }
        }
    }
}

// copy a 128x32 bf16 tile from global (ld elements) into padded smem
__device__ __forceinline__ void copy_tile16(uint32_t* dst, const __nv_bfloat16* __restrict__ src,
                                            int ld, int rowBase, int k0){
    int t = threadIdx.x;
    #pragma unroll
    for (int it = 0; it < 2; ++it){
        int idx = it*256 + t;
        int row = idx >> 2, seg = idx & 3;
        *reinterpret_cast<uint4*>(dst + row*SROW + seg*4) =
            *reinterpret_cast<const uint4*>(src + (size_t)(rowBase+row)*ld + k0 + seg*8);
    }
}

// ---------------- wmma GEMM, fp32 A converted in-kernel (gi/logits) ----------------
__device__ __forceinline__ void wmma_gemm(
    const float* __restrict__ Asrc, int lda, int mBase,
    const __nv_bfloat16* __restrict__ BHi, const __nv_bfloat16* __restrict__ BLo,
    int ldb, int nBase, int k0, int nChunks,
    float* __restrict__ dst, int ldd)
{
    __shared__ __align__(16) uint32_t sAHi[128*SROW], sALo[128*SROW];
    __shared__ __align__(16) uint32_t sBHi[128*SROW], sBLo[128*SROW];
    int t = threadIdx.x;
    FragC acc[2][4];
    #pragma unroll
    for (int mi = 0; mi < 2; ++mi)
        #pragma unroll
        for (int ni = 0; ni < 4; ++ni) wmma::fill_fragment(acc[mi][ni], 0.f);
    int w = t >> 5;
    int rowOff = (w&3)*32, colOff = (w>>2)*64;
    for (int c = 0; c < nChunks; ++c){
        int kc = k0 + c*32;
        #pragma unroll
        for (int it = 0; it < 2; ++it){
            int idx = it*256 + t;
            int row = idx >> 2, seg = idx & 3;
            const float* p = Asrc + (size_t)(mBase + row)*lda + kc + seg*8;
            float4 v0 = *reinterpret_cast<const float4*>(p);
            float4 v1 = *reinterpret_cast<const float4*>(p + 4);
            uint4 hi, lo; cvt16(v0, v1, hi, lo);
            *reinterpret_cast<uint4*>(sAHi + row*SROW + seg*4) = hi;
            *reinterpret_cast<uint4*>(sALo + row*SROW + seg*4) = lo;
        }
        copy_tile16(sBHi, BHi, ldb, nBase, kc);
        copy_tile16(sBLo, BLo, ldb, nBase, kc);
        __syncthreads();
        mma_stage(sAHi, sALo, sBHi, sBLo, rowOff, colOff, acc);
        __syncthreads();
    }
    #pragma unroll
    for (int mi = 0; mi < 2; ++mi)
        #pragma unroll
        for (int ni = 0; ni < 4; ++ni)
            wmma::store_matrix_sync(dst + (size_t)(mBase + rowOff + mi*16)*ldd
                                        + nBase + colOff + ni*16,
                                    acc[mi][ni], ldd, wmma::mem_row_major);
}

// ---------------- recurrence GEMM: N-tile 96, 128 CTAs, 2-stage pipeline ----------------
__global__ void __launch_bounds__(256, 1) k_ghB(){
    extern __shared__ __align__(16) uint32_t smb[];   // 2 stages x STG96
    int nt = blockIdx.x, kz = blockIdx.y;
    int nBase = nt*96, k0 = kz*256;
    int t = threadIdx.x, w = t >> 5;
    int rowOff = (w&3)*32, colOff = (w>>2)*48;
    // A copy coords: 512 tasks (128 rows x 4 segs), 2 per thread
    int ra0 = t >> 2,          sa0 = t & 3;
    int ra1 = (256+t) >> 2,    sa1 = t & 3;
    size_t a0 = (size_t)ra0*1024 + sa0*8,  a1 = (size_t)ra1*1024 + sa1*8;
    int da0 = ra0*SROW + sa0*4, da1 = ra1*SROW + sa1*4;
    // B copy coords: 384 tasks (96 rows x 4 segs); task t always, task 256+t if t<128
    int rb0 = t >> 2,          sb0 = t & 3;
    int rb1 = 64 + (t >> 2),   sb1 = t & 3;
    bool hasB1 = (t < 128);
    size_t b0 = (size_t)(nBase+rb0)*1024 + sb0*8;
    size_t b1 = (size_t)(nBase+rb1)*1024 + sb1*8;
    int db0 = rb0*SROW + sb0*4, db1 = rb1*SROW + sb1*4;

    FragC acc[2][3];
    #pragma unroll
    for (int mi = 0; mi < 2; ++mi)
        #pragma unroll
        for (int ni = 0; ni < 3; ++ni) wmma::fill_fragment(acc[mi][ni], 0.f);

    // prologue: chunk 0 -> stage 0
    {
        int kc = k0;
        uint32_t* st = smb;
        *reinterpret_cast<uint4*>(st + da0)        = *reinterpret_cast<const uint4*>(g_hH16 + a0 + kc);
        *reinterpret_cast<uint4*>(st + da1)        = *reinterpret_cast<const uint4*>(g_hH16 + a1 + kc);
        *reinterpret_cast<uint4*>(st + 2560 + da0) = *reinterpret_cast<const uint4*>(g_hL16 + a0 + kc);
        *reinterpret_cast<uint4*>(st + 2560 + da1) = *reinterpret_cast<const uint4*>(g_hL16 + a1 + kc);
        *reinterpret_cast<uint4*>(st + 5120 + db0) = *reinterpret_cast<const uint4*>(g_WhhHi + b0 + kc);
        *reinterpret_cast<uint4*>(st + 7040 + db0) = *reinterpret_cast<const uint4*>(g_WhhLo + b0 + kc);
        if (hasB1){
            *reinterpret_cast<uint4*>(st + 5120 + db1) = *reinterpret_cast<const uint4*>(g_WhhHi + b1 + kc);
            *reinterpret_cast<uint4*>(st + 7040 + db1) = *reinterpret_cast<const uint4*>(g_WhhLo + b1 + kc);
        }
    }
    __syncthreads();

    #pragma unroll
    for (int c = 0; c < 8; ++c){
        uint4 rAh0, rAh1, rAl0, rAl1, rBh0, rBh1, rBl0, rBl1;
        if (c < 7){
            int kc = k0 + (c+1)*32;
            rAh0 = *reinterpret_cast<const uint4*>(g_hH16 + a0 + kc);
            rAh1 = *reinterpret_cast<const uint4*>(g_hH16 + a1 + kc);
            rAl0 = *reinterpret_cast<const uint4*>(g_hL16 + a0 + kc);
            rAl1 = *reinterpret_cast<const uint4*>(g_hL16 + a1 + kc);
            rBh0 = *reinterpret_cast<const uint4*>(g_WhhHi + b0 + kc);
            rBl0 = *reinterpret_cast<const uint4*>(g_WhhLo + b0 + kc);
            if (hasB1){
                rBh1 = *reinterpret_cast<const uint4*>(g_WhhHi + b1 + kc);
                rBl1 = *reinterpret_cast<const uint4*>(g_WhhLo + b1 + kc);
            }
        }
        const uint32_t* st = smb + (c & 1)*STG96;
        mma_stage96(st, st + 2560, st + 5120, st + 7040, rowOff, colOff, acc);
        if (c < 7){
            uint32_t* dt = smb + ((c+1) & 1)*STG96;
            *reinterpret_cast<uint4*>(dt + da0)        = rAh0;
            *reinterpret_cast<uint4*>(dt + da1)        = rAh1;
            *reinterpret_cast<uint4*>(dt + 2560 + da0) = rAl0;
            *reinterpret_cast<uint4*>(dt + 2560 + da1) = rAl1;
            *reinterpret_cast<uint4*>(dt + 5120 + db0) = rBh0;
            *reinterpret_cast<uint4*>(dt + 7040 + db0) = rBl0;
            if (hasB1){
                *reinterpret_cast<uint4*>(dt + 5120 + db1) = rBh1;
                *reinterpret_cast<uint4*>(dt + 7040 + db1) = rBl1;
            }
        }
        __syncthreads();
    }
    float* dst = g_gh4 + (size_t)kz*Bb*G3;
    #pragma unroll
    for (int mi = 0; mi < 2; ++mi)
        #pragma unroll
        for (int ni = 0; ni < 3; ++ni)
            wmma::store_matrix_sync(dst + (size_t)(rowOff + mi*16)*G3
                                        + nBase + colOff + ni*16,
                                    acc[mi][ni], G3, wmma::mem_row_major);
}

// ---------------- prep kernels ----------------
__global__ void k_idx(const float* __restrict__ gt, const float* __restrict__ gotoken){
    int w = (blockIdx.x*blockDim.x + threadIdx.x) >> 5;
    int lane = threadIdx.x & 31;
    if (w >= RWS) return;
    int s = w / Bb, b = w % Bb;
    const float* src = (s == 0) ? gotoken : gt + ((size_t)b*Ss + (s-1))*Oo;
    int found = Oo - 1;
    for (int o = lane; o < Oo; o += 32)
        if (src[o] > 0.5f) found = o;
    #pragma unroll
    for (int off = 16; off; off >>= 1)
        found = min(found, __shfl_xor_sync(0xffffffffu, found, off));
    if (lane == 0) g_idx[w] = found;
}

__global__ void k_yT(const float* __restrict__ y){
    size_t t = (size_t)blockIdx.x*blockDim.x + threadIdx.x;
    if (t >= (size_t)RWS*Ii) return;
    int i = (int)(t % Ii); int r = (int)(t / Ii);
    int s = r / Bb, b = r % Bb;
    g_yT[t] = y[((size_t)b*Ss + s)*Ii + i];
}

__global__ void k_h0(const float* __restrict__ hx){
    int t = blockIdx.x*blockDim.x + threadIdx.x;
    if (t < Bb*Hh){
        float v = hx[t];
        g_hs[t] = v;
        __nv_bfloat16 h = __float2bfloat16(v);
        g_hH16[t] = h;
        g_hL16[t] = __float2bfloat16(v - __bfloat162float(h));
    }
}

__global__ void k_convWhh(const float* __restrict__ W){
    int t = blockIdx.x*blockDim.x + threadIdx.x;
    float v = W[t];
    __nv_bfloat16 h = __float2bfloat16(v);
    g_WhhHi[t] = h;
    g_WhhLo[t] = __float2bfloat16(v - __bfloat162float(h));
}
__global__ void k_convWih(const float* __restrict__ W){
    int t = blockIdx.x*blockDim.x + threadIdx.x;
    float v = W[t];
    __nv_bfloat16 h = __float2bfloat16(v);
    g_WihHi[t] = h;
    g_WihLo[t] = __float2bfloat16(v - __bfloat162float(h));
}
__global__ void k_convLw(const float* __restrict__ W){
    int t = blockIdx.x*blockDim.x + threadIdx.x;
    float v = W[t];
    __nv_bfloat16 h = __float2bfloat16(v);
    g_LwHi[t] = h;
    g_LwLo[t] = __float2bfloat16(v - __bfloat162float(h));
}

__global__ void k_prepT(const float* __restrict__ Wih){
    __shared__ float tile[32][33];
    int gB = blockIdx.x*32, oB = blockIdx.y*32;
    int tx = threadIdx.x, ty = threadIdx.y;
    #pragma unroll
    for (int j = 0; j < 32; j += 8)
        tile[ty+j][tx] = Wih[(size_t)(gB + ty + j)*1024 + 512 + oB + tx];
    __syncthreads();
    #pragma unroll
    for (int j = 0; j < 32; j += 8)
        g_WtgtT[(size_t)(oB + ty + j)*3072 + gB + tx] = tile[tx][ty+j];
}

// ---------------- GEMM kernels ----------------
__global__ void __launch_bounds__(256, 1) k_giW(){
    wmma_gemm(g_yT, 512, blockIdx.y*128,
              g_WihHi, g_WihLo, 1024, blockIdx.x*128, 0, 16,
              g_gi, 3072);
}

__global__ void __launch_bounds__(256, 1) k_lwW(){
    wmma_gemm(g_hsB, 1024, blockIdx.y*128,
              g_LwHi, g_LwLo, 1024, blockIdx.x*128, 0, 32,
              g_lg, 512);
}

// gi epilogue: add bih + one-hot gather column (25165824 float4 tasks)
__global__ void k_giBias(const float* __restrict__ bih){
    int idx = blockIdx.x*blockDim.x + threadIdx.x;
    int row = idx / 768;
    int n4 = (idx - row*768)*4;
    int id = g_idx[row];
    float4 v = *reinterpret_cast<float4*>(g_gi + (size_t)row*3072 + n4);
    float4 b = *reinterpret_cast<const float4*>(bih + n4);
    float4 wv = *reinterpret_cast<const float4*>(g_WtgtT + (size_t)id*3072 + n4);
    v.x += b.x + wv.x; v.y += b.y + wv.y; v.z += b.z + wv.z; v.w += b.w + wv.w;
    *reinterpret_cast<float4*>(g_gi + (size_t)row*3072 + n4) = v;
}

// ---------------- gates ----------------
__global__ void k_gates(const float* __restrict__ bhh, float* __restrict__ pre_out, int s){
    int t = blockIdx.x*blockDim.x + threadIdx.x;
    if (t >= Bb*Hh) return;
    int b = t >> 10, j = t & 1023;
    size_t gio = ((size_t)s*Bb + b)*G3 + j;
    float i_r = g_gi[gio], i_z = g_gi[gio + Hh], i_n = g_gi[gio + 2*Hh];
    size_t gho = (size_t)b*G3 + j;
    float h_r = bhh[j], h_z = bhh[Hh + j], h_n = bhh[2*Hh + j];
    #pragma unroll
    for (int kz = 0; kz < 4; ++kz){
        size_t o = (size_t)kz*Bb*G3 + gho;
        h_r += g_gh4[o]; h_z += g_gh4[o + Hh]; h_n += g_gh4[o + 2*Hh];
    }
    float rg = 1.f/(1.f + expf(-(i_r + h_r)));
    float zg = 1.f/(1.f + expf(-(i_z + h_z)));
    float pre = i_n + rg*h_n;
    float ng = tanhf(pre);
    float hp = g_hs[((size_t)s*Bb + b)*Hh + j];
    float hy = ng + zg*(hp - ng);
    g_hs [((size_t)(s+1)*Bb + b)*Hh + j] = hy;
    g_hsB[((size_t)b*Ss + s)*Hh + j]     = hy;
    pre_out[((size_t)b*Ss + s)*Hh + j]   = pre;
    __nv_bfloat16 hh = __float2bfloat16(hy);
    g_hH16[t] = hh;
    g_hL16[t] = __float2bfloat16(hy - __bfloat162float(hh));
}

// ---------------- softmax + argmax ----------------
__global__ void k_softmax(const float* __restrict__ lb,
                          float* __restrict__ probs, float* __restrict__ samp){
    __shared__ float sv[128];
    __shared__ int   si[128];
    int row = blockIdx.x;
    int t = threadIdx.x;
    const float* lgi = g_lg + (size_t)row*Oo;
    float v[4];
    #pragma unroll
    for (int i = 0; i < 4; ++i) v[i] = lgi[t + i*128] + lb[t + i*128];
    float lmax = v[0]; int lidx = t;
    #pragma unroll
    for (int i = 1; i < 4; ++i)
        if (v[i] > lmax){ lmax = v[i]; lidx = t + i*128; }
    sv[t] = lmax; si[t] = lidx; __syncthreads();
    for (int off = 64; off; off >>= 1){
        if (t < off){
            float v2 = sv[t+off]; int i2 = si[t+off];
            if (v2 > sv[t] || (v2 == sv[t] && i2 < si[t])){ sv[t] = v2; si[t] = i2; }
        }
        __syncthreads();
    }
    float rmax = sv[0]; int ridx = si[0];
    __syncthreads();
    float e[4]; float ls = 0.f;
    #pragma unroll
    for (int i = 0; i < 4; ++i){ e[i] = expf(v[i] - rmax); ls += e[i]; }
    sv[t] = ls; __syncthreads();
    for (int off = 64; off; off >>= 1){
        if (t < off) sv[t] += sv[t+off];
        __syncthreads();
    }
    float inv = 1.f/sv[0];
    float* lg = probs + (size_t)row*Oo;
    float* sp = samp + (size_t)row*Oo;
    #pragma unroll
    for (int i = 0; i < 4; ++i){
        int p = t + i*128;
        lg[p] = e[i]*inv;
        sp[p] = (p == ridx) ? 1.f : 0.f;
    }
}

__global__ void k_hxout(float* __restrict__ out){
    int t = blockIdx.x*blockDim.x + threadIdx.x;
    if (t < Bb*Hh) out[t] = g_hs[(size_t)Ss*Bb*Hh + t];
}

// ---------------- launch ----------------
extern "C" void kernel_launch(void* const* d_in, const int* in_sizes, int n_in,
                              void* d_out, int out_size){
    const float* y    = (const float*)d_in[0];
    const float* gt   = (const float*)d_in[1];
    const float* hx   = (const float*)d_in[2];
    const float* Wih  = (const float*)d_in[3];
    const float* bih  = (const float*)d_in[4];
    const float* Whh  = (const float*)d_in[5];
    const float* bhh  = (const float*)d_in[6];
    const float* lw   = (const float*)d_in[7];
    const float* lb   = (const float*)d_in[8];
    const float* gotk = (const float*)d_in[9];
    float* out = (float*)d_out;

    float* out_probs = out;
    float* out_pre   = out + (size_t)16777216;
    float* out_samp  = out + (size_t)50331648;
    float* out_hx    = out + (size_t)67108864;

    static int attr_set = 0;
    if (!attr_set){
        cudaFuncSetAttribute(k_ghB, cudaFuncAttributeMaxDynamicSharedMemorySize, 2*STG96*4);
        attr_set = 1;
    }

    k_idx    <<<RWS/8, 256>>>(gt, gotk);
    k_yT     <<<65536, 256>>>(y);
    k_h0     <<<Bb*Hh/256, 256>>>(hx);
    k_convWhh<<<12288, 256>>>(Whh);
    k_convWih<<<12288, 256>>>(Wih);
    k_convLw <<<2048, 256>>>(lw);
    k_prepT  <<<dim3(96, 16), dim3(32, 8)>>>(Wih);

    k_giW    <<<dim3(24, 256), 256>>>();
    k_giBias <<<98304, 256>>>(bih);

    for (int s = 0; s < Ss; ++s){
        k_ghB  <<<dim3(32, 4), 256, 2*STG96*4>>>();
        k_gates<<<Bb*Hh/256, 256>>>(bhh, out_pre, s);
    }

    k_lwW    <<<dim3(4, 256), 256>>>();
    k_softmax<<<RWS, 128>>>(lb, out_probs, out_samp);
    k_hxout  <<<Bb*Hh/256, 256>>>(out_hx);
}